// round 9
// baseline (speedup 1.0000x reference)
#include <cuda_runtime.h>
#include <cuda_bf16.h>
#include <cstdint>
#include <math.h>

#define NN 50000
#define EE 800000
#define FF 64

// ---------------- scratch (device globals; no allocation allowed) ----------------
__device__ float g_h[NN * FF];                // current node features
__device__ float g_AB[NN * 2 * FF];           // per-node A (cols 0..63) and B (cols 64..127)
__device__ float g_cat[(size_t)NN * 5 * FF];  // [N,320] fused features
__device__ int   g_deg[NN];
__device__ int   g_ptr[NN + 1];
__device__ int   g_cur[NN];
__device__ int   g_csrc[EE];
__device__ float g_Wab[2][FF * 2 * FF];       // [64][128] rearranged pre_W per layer
__device__ float g_Pb[2][FF];                 // folded bias (post_b @ lin_W + lin_b)
// bf16 hi/lo split of Wt[n][k] = (post_W @ lin_W)^T : [layer][hi/lo][64*320]
__device__ __nv_bfloat16 g_Wbf[2][2][64 * 320];

// device-side buffer id -> pointer (kernel_launch makes no pointer-resolving API calls)
__device__ __forceinline__ const float* resolve_src(int id, const float* ext) {
    switch (id) {
        case 0: return g_h;
        case 1: return g_AB;
        case 2: return g_cat;
        case 3: return g_Wab[0];
        case 4: return g_Wab[1];
        default: return ext;
    }
}
__device__ __forceinline__ float* resolve_dst(int id) {
    switch (id) {
        case 0: return g_h;
        case 1: return g_AB;
        default: return g_cat;
    }
}

// ---------------- fused prep ----------------
// blocks: [0,196) zero deg | [196,228) wab0 | [228,260) wab1 | 260 Pb0 | 261 Pb1
//         [262,342) Wbf0 | [342,422) Wbf1
__global__ void k_prep(const float* __restrict__ preW1, const float* __restrict__ preW2,
                       const float* __restrict__ postW1, const float* __restrict__ postb1,
                       const float* __restrict__ linW1, const float* __restrict__ linb1,
                       const float* __restrict__ postW2, const float* __restrict__ postb2,
                       const float* __restrict__ linW2, const float* __restrict__ linb2) {
    int b = blockIdx.x, tid = threadIdx.x;
    if (b < 196) {
        int i = b * 256 + tid;
        if (i < NN) g_deg[i] = 0;
        return;
    }
    if (b < 260) {  // wab: [64][128] rearranged pre_W
        int layer = (b < 228) ? 0 : 1;
        const float* preW = layer ? preW2 : preW1;
        int idx = (b - (layer ? 228 : 196)) * 256 + tid;  // < 8192
        int k = idx >> 7, c = idx & 127;
        g_Wab[layer][idx] = (c < 64) ? preW[k * 64 + c] : preW[(64 + k) * 64 + (c - 64)];
        return;
    }
    if (b < 262) {  // folded bias: Pb = post_b @ lin_W + lin_b
        int layer = b - 260;
        const float* postb = layer ? postb2 : postb1;
        const float* linW  = layer ? linW2  : linW1;
        const float* linb  = layer ? linb2  : linb1;
        if (tid < 64) {
            float s = linb[tid];
            #pragma unroll 8
            for (int k = 0; k < 64; k++) s += postb[k] * linW[k * 64 + tid];
            g_Pb[layer][tid] = s;
        }
        return;
    }
    {   // Wt[n][k] = sum_j postW[k][j]*linW[j][n], split hi/lo bf16, row-major [64][320]
        int layer = (b < 342) ? 0 : 1;
        const float* postW = layer ? postW2 : postW1;
        const float* linW  = layer ? linW2  : linW1;
        int idx = (b - (layer ? 342 : 262)) * 256 + tid;  // < 20480 = 64*320
        int n = idx / 320, k = idx % 320;
        float v = 0.f;
        #pragma unroll 8
        for (int j = 0; j < 64; j++) v += postW[k * 64 + j] * linW[j * 64 + n];
        __nv_bfloat16 hi = __float2bfloat16_rn(v);
        __nv_bfloat16 lo = __float2bfloat16_rn(v - __bfloat162float(hi));
        g_Wbf[layer][0][idx] = hi;
        g_Wbf[layer][1][idx] = lo;
    }
}

// ---------------- CSR build ----------------
__global__ void k_deg(const int* __restrict__ dst) {
    int e = blockIdx.x * blockDim.x + threadIdx.x;
    if (e < EE) atomicAdd(&g_deg[dst[e]], 1);
}

__global__ void k_scan() {  // single block, 1024 threads, shfl-based
    __shared__ int wsum[32];
    __shared__ int carry_s;
    int tid = threadIdx.x, lane = tid & 31, wid = tid >> 5;
    if (tid == 0) { carry_s = 0; g_ptr[0] = 0; }
    __syncthreads();
    for (int base = 0; base < NN; base += 1024) {
        int i = base + tid;
        int v = (i < NN) ? g_deg[i] : 0;
        int x = v;
        #pragma unroll
        for (int off = 1; off < 32; off <<= 1) {
            int y = __shfl_up_sync(0xffffffffu, x, off);
            if (lane >= off) x += y;
        }
        if (lane == 31) wsum[wid] = x;
        __syncthreads();
        if (wid == 0) {
            int s = wsum[lane];
            #pragma unroll
            for (int off = 1; off < 32; off <<= 1) {
                int y = __shfl_up_sync(0xffffffffu, s, off);
                if (lane >= off) s += y;
            }
            wsum[lane] = s;
        }
        __syncthreads();
        int incl = x + (wid ? wsum[wid - 1] : 0) + carry_s;
        if (i < NN) { g_ptr[i + 1] = incl; g_cur[i] = incl - v; }
        __syncthreads();
        if (tid == 1023) carry_s = incl;
        __syncthreads();
    }
}

__global__ void k_fill(const int* __restrict__ src, const int* __restrict__ dst) {
    int e = blockIdx.x * blockDim.x + threadIdx.x;
    if (e < EE) {
        int slot = atomicAdd(&g_cur[dst[e]], 1);
        g_csrc[slot] = src[e];
    }
}

// ---------------- SIMT tiled SGEMM (h0 and AB GEMMs), 8x4 per thread ----------------
template <int K, int NCOL, int ACT, int AID, int WID, int BID, int OID>
__global__ void __launch_bounds__(256) k_gemm(const float* __restrict__ Aext,
                                              const float* __restrict__ Wext,
                                              const float* __restrict__ Bext,
                                              int nrows) {
    const float* A = resolve_src(AID, Aext);
    const float* W = resolve_src(WID, Wext);
    const float* bias = (BID == -2) ? (const float*)0 : resolve_src(BID, Bext);
    float* C = resolve_dst(OID);

    constexpr int KC = 32;
    constexpr int CG = NCOL / 4;
    constexpr int RT = 256 / CG;
    constexpr int TM = RT * 8;
    __shared__ float As[KC][TM];
    __shared__ float Ws[KC][NCOL];
    int tid = threadIdx.x;
    int tx = tid % CG, ty = tid / CG;
    int row0 = blockIdx.x * TM;
    float acc[8][4] = {};
    for (int kc = 0; kc < K; kc += KC) {
        #pragma unroll
        for (int f = 0; f < (TM * KC / 4) / 256; f++) {
            int idx = tid + f * 256;
            int r = idx / (KC / 4);
            int kq = idx % (KC / 4);
            float4 v = make_float4(0.f, 0.f, 0.f, 0.f);
            if (row0 + r < nrows)
                v = *reinterpret_cast<const float4*>(&A[(size_t)(row0 + r) * K + kc + kq * 4]);
            As[kq * 4 + 0][r] = v.x;
            As[kq * 4 + 1][r] = v.y;
            As[kq * 4 + 2][r] = v.z;
            As[kq * 4 + 3][r] = v.w;
        }
        #pragma unroll
        for (int f = 0; f < (KC * NCOL / 4) / 256; f++) {
            int idx = tid + f * 256;
            int kr = idx / CG;
            int cq = idx % CG;
            *reinterpret_cast<float4*>(&Ws[kr][cq * 4]) =
                *reinterpret_cast<const float4*>(&W[(size_t)(kc + kr) * NCOL + cq * 4]);
        }
        __syncthreads();
        #pragma unroll
        for (int k = 0; k < KC; k++) {
            float4 a0 = *reinterpret_cast<const float4*>(&As[k][ty * 8]);
            float4 a1 = *reinterpret_cast<const float4*>(&As[k][ty * 8 + 4]);
            float4 w = *reinterpret_cast<const float4*>(&Ws[k][tx * 4]);
            float av[8] = {a0.x, a0.y, a0.z, a0.w, a1.x, a1.y, a1.z, a1.w};
            float wv[4] = {w.x, w.y, w.z, w.w};
            #pragma unroll
            for (int r = 0; r < 8; r++)
                #pragma unroll
                for (int c = 0; c < 4; c++) acc[r][c] = fmaf(av[r], wv[c], acc[r][c]);
        }
        __syncthreads();
    }
    #pragma unroll
    for (int r = 0; r < 8; r++) {
        int row = row0 + ty * 8 + r;
        if (row < nrows) {
            #pragma unroll
            for (int c = 0; c < 4; c++) {
                float v = acc[r][c];
                int col = tx * 4 + c;
                if (bias) v += bias[col];
                if (ACT == 1) v = (v > 0.f) ? v : 0.2f * v;
                if (ACT == 2) v = fmaxf(v, 0.f);
                C[(size_t)row * NCOL + col] = v;
            }
        }
    }
}

// ---------------- HMMA (mma.sync, base ISA) GEMM: g_cat[128 x 320] @ Wt -> 64 cols -------
__device__ __forceinline__ void mma_bf16(float* c, const uint32_t* a, const uint32_t* b) {
    asm volatile(
        "mma.sync.aligned.m16n8k16.row.col.f32.bf16.bf16.f32 "
        "{%0,%1,%2,%3}, {%4,%5,%6,%7}, {%8,%9}, {%0,%1,%2,%3};"
        : "+f"(c[0]), "+f"(c[1]), "+f"(c[2]), "+f"(c[3])
        : "r"(a[0]), "r"(a[1]), "r"(a[2]), "r"(a[3]), "r"(b[0]), "r"(b[1]));
}
__device__ __forceinline__ void cvt_split(float2 v, uint32_t& hi, uint32_t& lo) {
    __nv_bfloat16 hx = __float2bfloat16_rn(v.x), hy = __float2bfloat16_rn(v.y);
    __nv_bfloat16 lx = __float2bfloat16_rn(v.x - __bfloat162float(hx));
    __nv_bfloat16 ly = __float2bfloat16_rn(v.y - __bfloat162float(hy));
    __nv_bfloat162 h(hx, hy), l(lx, ly);
    hi = *reinterpret_cast<uint32_t*>(&h);
    lo = *reinterpret_cast<uint32_t*>(&l);
}

// 256 threads = 8 warps; block tile 128 rows; warp tile 16 rows x 64 cols.
// 3-product split-precision: hi*hi + lo*hi + hi*lo (error ~ eps^2 ~ 1.5e-5).
template <int LAYER, int FINAL>
__global__ void __launch_bounds__(256) k_hmma(const float* __restrict__ W2,
                                              const float* __restrict__ b2,
                                              float* __restrict__ outp) {
    int tid = threadIdx.x, wid = tid >> 5, lane = tid & 31;
    int gr = lane >> 2, qc = lane & 3;
    int ra = blockIdx.x * 128 + wid * 16 + gr;   // rows gr and gr+8 of warp tile
    int rb = ra + 8;
    bool va = ra < NN, vb = rb < NN;
    const float* rowa = &g_cat[(size_t)ra * 320];
    const float* rowb = &g_cat[(size_t)rb * 320];
    const __nv_bfloat16* Wh = g_Wbf[LAYER][0];
    const __nv_bfloat16* Wl = g_Wbf[LAYER][1];

    float acc[8][4] = {};
    #pragma unroll 4
    for (int ks = 0; ks < 20; ks++) {
        int k0 = ks * 16 + qc * 2;
        float2 z = make_float2(0.f, 0.f);
        float2 a00 = va ? *reinterpret_cast<const float2*>(rowa + k0)     : z;
        float2 a01 = va ? *reinterpret_cast<const float2*>(rowa + k0 + 8) : z;
        float2 a10 = vb ? *reinterpret_cast<const float2*>(rowb + k0)     : z;
        float2 a11 = vb ? *reinterpret_cast<const float2*>(rowb + k0 + 8) : z;
        uint32_t ah[4], al[4];
        cvt_split(a00, ah[0], al[0]);
        cvt_split(a10, ah[1], al[1]);
        cvt_split(a01, ah[2], al[2]);
        cvt_split(a11, ah[3], al[3]);
        #pragma unroll
        for (int nt = 0; nt < 8; nt++) {
            int n = nt * 8 + gr;
            const __nv_bfloat16* wph = Wh + n * 320 + k0;
            const __nv_bfloat16* wpl = Wl + n * 320 + k0;
            uint32_t bh[2], bl[2];
            bh[0] = *reinterpret_cast<const uint32_t*>(wph);
            bh[1] = *reinterpret_cast<const uint32_t*>(wph + 8);
            bl[0] = *reinterpret_cast<const uint32_t*>(wpl);
            bl[1] = *reinterpret_cast<const uint32_t*>(wpl + 8);
            mma_bf16(acc[nt], ah, bh);
            mma_bf16(acc[nt], al, bh);
            mma_bf16(acc[nt], ah, bl);
        }
    }

    if (FINAL) {
        // out[row] = sum_col relu(acc + Pb[col]) * W2[col] + b2
        float pa = 0.f, pb = 0.f;
        #pragma unroll
        for (int nt = 0; nt < 8; nt++) {
            int col = nt * 8 + qc * 2;
            float pb0 = g_Pb[LAYER][col], pb1 = g_Pb[LAYER][col + 1];
            float w0 = W2[col], w1 = W2[col + 1];
            pa = fmaf(fmaxf(acc[nt][0] + pb0, 0.f), w0, pa);
            pa = fmaf(fmaxf(acc[nt][1] + pb1, 0.f), w1, pa);
            pb = fmaf(fmaxf(acc[nt][2] + pb0, 0.f), w0, pb);
            pb = fmaf(fmaxf(acc[nt][3] + pb1, 0.f), w1, pb);
        }
        pa += __shfl_xor_sync(0xffffffffu, pa, 1);
        pa += __shfl_xor_sync(0xffffffffu, pa, 2);
        pb += __shfl_xor_sync(0xffffffffu, pb, 1);
        pb += __shfl_xor_sync(0xffffffffu, pb, 2);
        if (qc == 0) {
            float bv = b2[0];
            if (va) outp[ra] = pa + bv;
            if (vb) outp[rb] = pb + bv;
        }
    } else {
        // g_h[row][col] = relu(acc + Pb[col])
        #pragma unroll
        for (int nt = 0; nt < 8; nt++) {
            int col = nt * 8 + qc * 2;
            float pb0 = g_Pb[LAYER][col], pb1 = g_Pb[LAYER][col + 1];
            if (va) {
                float2 o = make_float2(fmaxf(acc[nt][0] + pb0, 0.f),
                                       fmaxf(acc[nt][1] + pb1, 0.f));
                *reinterpret_cast<float2*>(&g_h[(size_t)ra * 64 + col]) = o;
            }
            if (vb) {
                float2 o = make_float2(fmaxf(acc[nt][2] + pb0, 0.f),
                                       fmaxf(acc[nt][3] + pb1, 0.f));
                *reinterpret_cast<float2*>(&g_h[(size_t)rb * 64 + col]) = o;
            }
        }
    }
}

// ---------------- aggregation: segment sum/max of B over rank-sorted CSR, build cat --------
#define MAXD 192
__global__ void __launch_bounds__(256) k_agg(const float* __restrict__ preb) {
    __shared__ int ssrc[4][MAXD];
    __shared__ int ssrt[4][MAXD];
    int g = threadIdx.x >> 6;
    int t = threadIdx.x & 63;
    int node = blockIdx.x * 4 + g;
    bool valid = node < NN;
    int beg = 0, end = 0;
    if (valid) { beg = g_ptr[node]; end = g_ptr[node + 1]; }
    int deg = end - beg;
    bool small = valid && (deg <= MAXD);
    if (small) {
        for (int e = t; e < deg; e += 64) ssrc[g][e] = g_csrc[beg + e];
    }
    __syncthreads();
    if (small) {
        for (int i = t; i < deg; i += 64) {
            int v = ssrc[g][i];
            int rank = 0;
            for (int j = 0; j < deg; j++) {
                int u = ssrc[g][j];
                rank += (u < v) || (u == v && j < i);
            }
            ssrt[g][rank] = v;
        }
    }
    __syncthreads();
    if (!valid) return;
    float sum = 0.f, mx = -3.4e38f;
    if (small) {
        #pragma unroll 4
        for (int e = 0; e < deg; e++) {
            float v = g_AB[(size_t)ssrt[g][e] * 128 + 64 + t];
            sum += v;
            mx = fmaxf(mx, v);
        }
    } else {
        for (int e = beg; e < end; e++) {
            float v = g_AB[(size_t)g_csrc[e] * 128 + 64 + t];
            sum += v;
            mx = fmaxf(mx, v);
        }
    }
    float hx = g_h[node * 64 + t];
    float* cr = &g_cat[(size_t)node * 320];
    cr[t] = hx;
    if (deg == 0) {
        cr[64 + t] = 0.f; cr[128 + t] = 0.f; cr[192 + t] = 0.f; cr[256 + t] = 0.f;
    } else {
        float bA = g_AB[(size_t)node * 128 + t] + preb[t];
        float mean = bA + sum / (float)deg;
        float mxv = bA + mx;
        float sa = 2.8332133440562162f / logf((float)deg + 1.0f);  // log(17)/log(deg+1)
        float sl = (float)deg * 0.0625f;                            // deg/16
        cr[64 + t] = mean * sa;
        cr[128 + t] = mxv * sa;
        cr[192 + t] = mean * sl;
        cr[256 + t] = mxv * sl;
    }
}

// ---------------- launch: kernel launches ONLY ----------------
extern "C" void kernel_launch(void* const* d_in, const int* in_sizes, int n_in,
                              void* d_out, int out_size) {
    (void)in_sizes; (void)n_in; (void)out_size;
    const float* x   = (const float*)d_in[0];
    const int*   ei  = (const int*)d_in[2];
    const float* W0  = (const float*)d_in[3];
    const float* b0  = (const float*)d_in[4];
    const float* preW1  = (const float*)d_in[5];
    const float* preB1  = (const float*)d_in[6];
    const float* postW1 = (const float*)d_in[7];
    const float* postB1 = (const float*)d_in[8];
    const float* linW1  = (const float*)d_in[9];
    const float* linB1  = (const float*)d_in[10];
    const float* preW2  = (const float*)d_in[11];
    const float* preB2  = (const float*)d_in[12];
    const float* postW2 = (const float*)d_in[13];
    const float* postB2 = (const float*)d_in[14];
    const float* linW2  = (const float*)d_in[15];
    const float* linB2  = (const float*)d_in[16];
    const float* W2 = (const float*)d_in[17];
    const float* b2 = (const float*)d_in[18];
    float* out = (float*)d_out;

    const int* src = ei;
    const int* dst = ei + EE;

    // prep + CSR build
    k_prep<<<422, 256>>>(preW1, preW2, postW1, postB1, linW1, linB1,
                         postW2, postB2, linW2, linB2);
    k_deg<<<(EE + 255) / 256, 256>>>(dst);
    k_scan<<<1, 1024>>>();
    k_fill<<<(EE + 255) / 256, 256>>>(src, dst);

    // h0 = leaky_relu(x @ W0 + b0)
    k_gemm<128, 64, 1, -1, -1, -1, 0><<<(NN + 127) / 128, 256>>>(x, W0, b0, NN);

    // layer 1
    k_gemm<64, 128, 0, 0, 3, -2, 1><<<(NN + 63) / 64, 256>>>(0, 0, 0, NN);
    k_agg<<<(NN + 3) / 4, 256>>>(preB1);
    k_hmma<0, 0><<<(NN + 127) / 128, 256>>>(0, 0, 0);

    // layer 2 (HMMA GEMM fuses relu + out = h . W2 + b2)
    k_gemm<64, 128, 0, 0, 4, -2, 1><<<(NN + 63) / 64, 256>>>(0, 0, 0, NN);
    k_agg<<<(NN + 3) / 4, 256>>>(preB2);
    k_hmma<1, 1><<<(NN + 127) / 128, 256>>>(W2, b2, out);
}

// round 10
// speedup vs baseline: 1.3030x; 1.3030x over previous
#include <cuda_runtime.h>
#include <cuda_bf16.h>
#include <cstdint>
#include <math.h>

#define NN 50000
#define EE 800000
#define FF 64

// ---------------- scratch (device globals; no allocation allowed) ----------------
__device__ float g_h[NN * FF];                // current node features
__device__ float g_AB[NN * 2 * FF];           // per-node A (cols 0..63) and B (cols 64..127)
__device__ float g_cat[(size_t)NN * 5 * FF];  // [N,320] fused features
__device__ int   g_deg[NN];
__device__ int   g_ptr[NN + 1];
__device__ int   g_cur[NN];
__device__ int   g_csrc[EE];
__device__ float g_Wab[2][FF * 2 * FF];       // [64][128] rearranged pre_W per layer
__device__ float g_Pb[2][FF];                 // folded bias (post_b @ lin_W + lin_b)
// bf16 hi/lo split of Wt[n][k] = (post_W @ lin_W)^T : [layer][hi/lo][64*320]
__device__ __nv_bfloat16 g_Wbf[2][2][64 * 320];

// device-side buffer id -> pointer (kernel_launch makes no pointer-resolving API calls)
__device__ __forceinline__ const float* resolve_src(int id, const float* ext) {
    switch (id) {
        case 0: return g_h;
        case 1: return g_AB;
        case 2: return g_cat;
        case 3: return g_Wab[0];
        case 4: return g_Wab[1];
        default: return ext;
    }
}
__device__ __forceinline__ float* resolve_dst(int id) {
    switch (id) {
        case 0: return g_h;
        case 1: return g_AB;
        default: return g_cat;
    }
}

// ---------------- fused prep ----------------
// blocks: [0,196) zero deg | [196,228) wab0 | [228,260) wab1 | 260 Pb0 | 261 Pb1
//         [262,342) Wbf0 | [342,422) Wbf1
__global__ void k_prep(const float* __restrict__ preW1, const float* __restrict__ preW2,
                       const float* __restrict__ postW1, const float* __restrict__ postb1,
                       const float* __restrict__ linW1, const float* __restrict__ linb1,
                       const float* __restrict__ postW2, const float* __restrict__ postb2,
                       const float* __restrict__ linW2, const float* __restrict__ linb2) {
    int b = blockIdx.x, tid = threadIdx.x;
    if (b < 196) {
        int i = b * 256 + tid;
        if (i < NN) g_deg[i] = 0;
        return;
    }
    if (b < 260) {  // wab: [64][128] rearranged pre_W
        int layer = (b < 228) ? 0 : 1;
        const float* preW = layer ? preW2 : preW1;
        int idx = (b - (layer ? 228 : 196)) * 256 + tid;  // < 8192
        int k = idx >> 7, c = idx & 127;
        g_Wab[layer][idx] = (c < 64) ? preW[k * 64 + c] : preW[(64 + k) * 64 + (c - 64)];
        return;
    }
    if (b < 262) {  // folded bias: Pb = post_b @ lin_W + lin_b
        int layer = b - 260;
        const float* postb = layer ? postb2 : postb1;
        const float* linW  = layer ? linW2  : linW1;
        const float* linb  = layer ? linb2  : linb1;
        if (tid < 64) {
            float s = linb[tid];
            #pragma unroll 8
            for (int k = 0; k < 64; k++) s += postb[k] * linW[k * 64 + tid];
            g_Pb[layer][tid] = s;
        }
        return;
    }
    {   // Wt[n][k] = sum_j postW[k][j]*linW[j][n], split hi/lo bf16, row-major [64][320]
        int layer = (b < 342) ? 0 : 1;
        const float* postW = layer ? postW2 : postW1;
        const float* linW  = layer ? linW2  : linW1;
        int idx = (b - (layer ? 342 : 262)) * 256 + tid;  // < 20480 = 64*320
        int n = idx / 320, k = idx % 320;
        float v = 0.f;
        #pragma unroll 8
        for (int j = 0; j < 64; j++) v += postW[k * 64 + j] * linW[j * 64 + n];
        __nv_bfloat16 hi = __float2bfloat16_rn(v);
        __nv_bfloat16 lo = __float2bfloat16_rn(v - __bfloat162float(hi));
        g_Wbf[layer][0][idx] = hi;
        g_Wbf[layer][1][idx] = lo;
    }
}

// ---------------- CSR build ----------------
__global__ void k_deg(const int* __restrict__ dst) {
    int e = blockIdx.x * blockDim.x + threadIdx.x;
    if (e < EE) atomicAdd(&g_deg[dst[e]], 1);
}

__global__ void k_scan() {  // single block, 1024 threads, shfl-based
    __shared__ int wsum[32];
    __shared__ int carry_s;
    int tid = threadIdx.x, lane = tid & 31, wid = tid >> 5;
    if (tid == 0) { carry_s = 0; g_ptr[0] = 0; }
    __syncthreads();
    for (int base = 0; base < NN; base += 1024) {
        int i = base + tid;
        int v = (i < NN) ? g_deg[i] : 0;
        int x = v;
        #pragma unroll
        for (int off = 1; off < 32; off <<= 1) {
            int y = __shfl_up_sync(0xffffffffu, x, off);
            if (lane >= off) x += y;
        }
        if (lane == 31) wsum[wid] = x;
        __syncthreads();
        if (wid == 0) {
            int s = wsum[lane];
            #pragma unroll
            for (int off = 1; off < 32; off <<= 1) {
                int y = __shfl_up_sync(0xffffffffu, s, off);
                if (lane >= off) s += y;
            }
            wsum[lane] = s;
        }
        __syncthreads();
        int incl = x + (wid ? wsum[wid - 1] : 0) + carry_s;
        if (i < NN) { g_ptr[i + 1] = incl; g_cur[i] = incl - v; }
        __syncthreads();
        if (tid == 1023) carry_s = incl;
        __syncthreads();
    }
}

__global__ void k_fill(const int* __restrict__ src, const int* __restrict__ dst) {
    int e = blockIdx.x * blockDim.x + threadIdx.x;
    if (e < EE) {
        int slot = atomicAdd(&g_cur[dst[e]], 1);
        g_csrc[slot] = src[e];
    }
}

// ---------------- SIMT tiled SGEMM (h0 and AB GEMMs), 8x4 per thread ----------------
template <int K, int NCOL, int ACT, int AID, int WID, int BID, int OID>
__global__ void __launch_bounds__(256) k_gemm(const float* __restrict__ Aext,
                                              const float* __restrict__ Wext,
                                              const float* __restrict__ Bext,
                                              int nrows) {
    const float* A = resolve_src(AID, Aext);
    const float* W = resolve_src(WID, Wext);
    const float* bias = (BID == -2) ? (const float*)0 : resolve_src(BID, Bext);
    float* C = resolve_dst(OID);

    constexpr int KC = 32;
    constexpr int CG = NCOL / 4;
    constexpr int RT = 256 / CG;
    constexpr int TM = RT * 8;
    __shared__ float As[KC][TM];
    __shared__ float Ws[KC][NCOL];
    int tid = threadIdx.x;
    int tx = tid % CG, ty = tid / CG;
    int row0 = blockIdx.x * TM;
    float acc[8][4] = {};
    for (int kc = 0; kc < K; kc += KC) {
        #pragma unroll
        for (int f = 0; f < (TM * KC / 4) / 256; f++) {
            int idx = tid + f * 256;
            int r = idx / (KC / 4);
            int kq = idx % (KC / 4);
            float4 v = make_float4(0.f, 0.f, 0.f, 0.f);
            if (row0 + r < nrows)
                v = *reinterpret_cast<const float4*>(&A[(size_t)(row0 + r) * K + kc + kq * 4]);
            As[kq * 4 + 0][r] = v.x;
            As[kq * 4 + 1][r] = v.y;
            As[kq * 4 + 2][r] = v.z;
            As[kq * 4 + 3][r] = v.w;
        }
        #pragma unroll
        for (int f = 0; f < (KC * NCOL / 4) / 256; f++) {
            int idx = tid + f * 256;
            int kr = idx / CG;
            int cq = idx % CG;
            *reinterpret_cast<float4*>(&Ws[kr][cq * 4]) =
                *reinterpret_cast<const float4*>(&W[(size_t)(kc + kr) * NCOL + cq * 4]);
        }
        __syncthreads();
        #pragma unroll
        for (int k = 0; k < KC; k++) {
            float4 a0 = *reinterpret_cast<const float4*>(&As[k][ty * 8]);
            float4 a1 = *reinterpret_cast<const float4*>(&As[k][ty * 8 + 4]);
            float4 w = *reinterpret_cast<const float4*>(&Ws[k][tx * 4]);
            float av[8] = {a0.x, a0.y, a0.z, a0.w, a1.x, a1.y, a1.z, a1.w};
            float wv[4] = {w.x, w.y, w.z, w.w};
            #pragma unroll
            for (int r = 0; r < 8; r++)
                #pragma unroll
                for (int c = 0; c < 4; c++) acc[r][c] = fmaf(av[r], wv[c], acc[r][c]);
        }
        __syncthreads();
    }
    #pragma unroll
    for (int r = 0; r < 8; r++) {
        int row = row0 + ty * 8 + r;
        if (row < nrows) {
            #pragma unroll
            for (int c = 0; c < 4; c++) {
                float v = acc[r][c];
                int col = tx * 4 + c;
                if (bias) v += bias[col];
                if (ACT == 1) v = (v > 0.f) ? v : 0.2f * v;
                if (ACT == 2) v = fmaxf(v, 0.f);
                C[(size_t)row * NCOL + col] = v;
            }
        }
    }
}

// ---------------- HMMA (mma.sync) GEMM with SMEM-staged W: g_cat[128x320] @ Wt -> 64 ------
__device__ __forceinline__ void mma_bf16(float* c, const uint32_t* a, const uint32_t* b) {
    asm volatile(
        "mma.sync.aligned.m16n8k16.row.col.f32.bf16.bf16.f32 "
        "{%0,%1,%2,%3}, {%4,%5,%6,%7}, {%8,%9}, {%0,%1,%2,%3};"
        : "+f"(c[0]), "+f"(c[1]), "+f"(c[2]), "+f"(c[3])
        : "r"(a[0]), "r"(a[1]), "r"(a[2]), "r"(a[3]), "r"(b[0]), "r"(b[1]));
}
__device__ __forceinline__ void cvt_split(float2 v, uint32_t& hi, uint32_t& lo) {
    __nv_bfloat16 hx = __float2bfloat16_rn(v.x), hy = __float2bfloat16_rn(v.y);
    __nv_bfloat16 lx = __float2bfloat16_rn(v.x - __bfloat162float(hx));
    __nv_bfloat16 ly = __float2bfloat16_rn(v.y - __bfloat162float(hy));
    __nv_bfloat162 h(hx, hy), l(lx, ly);
    hi = *reinterpret_cast<uint32_t*>(&h);
    lo = *reinterpret_cast<uint32_t*>(&l);
}

// 256 threads = 8 warps; block tile 128 rows; warp tile 16 rows x 64 cols.
// W staged in SMEM per k-half (stride 84 words/row; (20*gr+qc) mod 32 -> conflict-free).
// 3-product split-precision: hi*hi + lo*hi + hi*lo (error ~ eps^2 ~ 1.5e-5).
#define WSTR 84   // u32 words per row (168 bf16)
template <int LAYER, int FINAL>
__global__ void __launch_bounds__(256) k_hmma(const float* __restrict__ W2,
                                              const float* __restrict__ b2,
                                              float* __restrict__ outp) {
    __shared__ uint32_t Wsh[2][64 * WSTR];   // [hi/lo][64 rows x 84 words] = 43008 B
    int tid = threadIdx.x, wid = tid >> 5, lane = tid & 31;
    int gr = lane >> 2, qc = lane & 3;
    int ra = blockIdx.x * 128 + wid * 16 + gr;   // rows gr and gr+8 of warp tile
    int rb = ra + 8;
    bool va = ra < NN, vb = rb < NN;
    const float* rowa = &g_cat[(size_t)ra * 320];
    const float* rowb = &g_cat[(size_t)rb * 320];
    const uint32_t* srcH = reinterpret_cast<const uint32_t*>(g_Wbf[LAYER][0]);
    const uint32_t* srcL = reinterpret_cast<const uint32_t*>(g_Wbf[LAYER][1]);

    float acc[8][4] = {};
    for (int half = 0; half < 2; half++) {
        if (half) __syncthreads();   // prior half fully consumed
        // stage this k-half of W (64 rows x 80 words each mat), coalesced
        for (int idx = tid; idx < 5120; idx += 256) {
            int n = idx >> 6;            // 5120/64... careful: 80 words/row
            n = idx / 80;
            int kw = idx - n * 80;
            Wsh[0][n * WSTR + kw] = srcH[n * 160 + half * 80 + kw];
            Wsh[1][n * WSTR + kw] = srcL[n * 160 + half * 80 + kw];
        }
        __syncthreads();
        #pragma unroll 2
        for (int ksl = 0; ksl < 10; ksl++) {
            int k0 = half * 160 + ksl * 16 + qc * 2;   // global k for A
            float2 z = make_float2(0.f, 0.f);
            float2 a00 = va ? *reinterpret_cast<const float2*>(rowa + k0)     : z;
            float2 a01 = va ? *reinterpret_cast<const float2*>(rowa + k0 + 8) : z;
            float2 a10 = vb ? *reinterpret_cast<const float2*>(rowb + k0)     : z;
            float2 a11 = vb ? *reinterpret_cast<const float2*>(rowb + k0 + 8) : z;
            uint32_t ah[4], al[4];
            cvt_split(a00, ah[0], al[0]);
            cvt_split(a10, ah[1], al[1]);
            cvt_split(a01, ah[2], al[2]);
            cvt_split(a11, ah[3], al[3]);
            int kw = ksl * 8 + qc;   // word offset within smem row
            #pragma unroll
            for (int nt = 0; nt < 8; nt++) {
                int n = nt * 8 + gr;
                uint32_t bh[2], bl[2];
                bh[0] = Wsh[0][n * WSTR + kw];
                bh[1] = Wsh[0][n * WSTR + kw + 4];
                bl[0] = Wsh[1][n * WSTR + kw];
                bl[1] = Wsh[1][n * WSTR + kw + 4];
                mma_bf16(acc[nt], ah, bh);
                mma_bf16(acc[nt], al, bh);
                mma_bf16(acc[nt], ah, bl);
            }
        }
    }

    if (FINAL) {
        // out[row] = sum_col relu(acc + Pb[col]) * W2[col] + b2
        float pa = 0.f, pb = 0.f;
        #pragma unroll
        for (int nt = 0; nt < 8; nt++) {
            int col = nt * 8 + qc * 2;
            float pb0 = g_Pb[LAYER][col], pb1 = g_Pb[LAYER][col + 1];
            float w0 = W2[col], w1 = W2[col + 1];
            pa = fmaf(fmaxf(acc[nt][0] + pb0, 0.f), w0, pa);
            pa = fmaf(fmaxf(acc[nt][1] + pb1, 0.f), w1, pa);
            pb = fmaf(fmaxf(acc[nt][2] + pb0, 0.f), w0, pb);
            pb = fmaf(fmaxf(acc[nt][3] + pb1, 0.f), w1, pb);
        }
        pa += __shfl_xor_sync(0xffffffffu, pa, 1);
        pa += __shfl_xor_sync(0xffffffffu, pa, 2);
        pb += __shfl_xor_sync(0xffffffffu, pb, 1);
        pb += __shfl_xor_sync(0xffffffffu, pb, 2);
        if (qc == 0) {
            float bv = b2[0];
            if (va) outp[ra] = pa + bv;
            if (vb) outp[rb] = pb + bv;
        }
    } else {
        // g_h[row][col] = relu(acc + Pb[col])
        #pragma unroll
        for (int nt = 0; nt < 8; nt++) {
            int col = nt * 8 + qc * 2;
            float pb0 = g_Pb[LAYER][col], pb1 = g_Pb[LAYER][col + 1];
            if (va) {
                float2 o = make_float2(fmaxf(acc[nt][0] + pb0, 0.f),
                                       fmaxf(acc[nt][1] + pb1, 0.f));
                *reinterpret_cast<float2*>(&g_h[(size_t)ra * 64 + col]) = o;
            }
            if (vb) {
                float2 o = make_float2(fmaxf(acc[nt][2] + pb0, 0.f),
                                       fmaxf(acc[nt][3] + pb1, 0.f));
                *reinterpret_cast<float2*>(&g_h[(size_t)rb * 64 + col]) = o;
            }
        }
    }
}

// ---------------- aggregation: segment sum/max of B over rank-sorted CSR, build cat --------
#define MAXD 192
__global__ void __launch_bounds__(256) k_agg(const float* __restrict__ preb) {
    __shared__ int ssrc[4][MAXD];
    __shared__ int ssrt[4][MAXD];
    int g = threadIdx.x >> 6;
    int t = threadIdx.x & 63;
    int node = blockIdx.x * 4 + g;
    bool valid = node < NN;
    int beg = 0, end = 0;
    if (valid) { beg = g_ptr[node]; end = g_ptr[node + 1]; }
    int deg = end - beg;
    bool small = valid && (deg <= MAXD);
    if (small) {
        for (int e = t; e < deg; e += 64) ssrc[g][e] = g_csrc[beg + e];
    }
    __syncthreads();
    if (small) {
        for (int i = t; i < deg; i += 64) {
            int v = ssrc[g][i];
            int rank = 0;
            for (int j = 0; j < deg; j++) {
                int u = ssrc[g][j];
                rank += (u < v) || (u == v && j < i);
            }
            ssrt[g][rank] = v;
        }
    }
    __syncthreads();
    if (!valid) return;
    float sum = 0.f, mx = -3.4e38f;
    if (small) {
        #pragma unroll 4
        for (int e = 0; e < deg; e++) {
            float v = g_AB[(size_t)ssrt[g][e] * 128 + 64 + t];
            sum += v;
            mx = fmaxf(mx, v);
        }
    } else {
        for (int e = beg; e < end; e++) {
            float v = g_AB[(size_t)g_csrc[e] * 128 + 64 + t];
            sum += v;
            mx = fmaxf(mx, v);
        }
    }
    float hx = g_h[node * 64 + t];
    float* cr = &g_cat[(size_t)node * 320];
    cr[t] = hx;
    if (deg == 0) {
        cr[64 + t] = 0.f; cr[128 + t] = 0.f; cr[192 + t] = 0.f; cr[256 + t] = 0.f;
    } else {
        float bA = g_AB[(size_t)node * 128 + t] + preb[t];
        float mean = bA + sum / (float)deg;
        float mxv = bA + mx;
        float sa = 2.8332133440562162f / logf((float)deg + 1.0f);  // log(17)/log(deg+1)
        float sl = (float)deg * 0.0625f;                            // deg/16
        cr[64 + t] = mean * sa;
        cr[128 + t] = mxv * sa;
        cr[192 + t] = mean * sl;
        cr[256 + t] = mxv * sl;
    }
}

// ---------------- launch: kernel launches ONLY ----------------
extern "C" void kernel_launch(void* const* d_in, const int* in_sizes, int n_in,
                              void* d_out, int out_size) {
    (void)in_sizes; (void)n_in; (void)out_size;
    const float* x   = (const float*)d_in[0];
    const int*   ei  = (const int*)d_in[2];
    const float* W0  = (const float*)d_in[3];
    const float* b0  = (const float*)d_in[4];
    const float* preW1  = (const float*)d_in[5];
    const float* preB1  = (const float*)d_in[6];
    const float* postW1 = (const float*)d_in[7];
    const float* postB1 = (const float*)d_in[8];
    const float* linW1  = (const float*)d_in[9];
    const float* linB1  = (const float*)d_in[10];
    const float* preW2  = (const float*)d_in[11];
    const float* preB2  = (const float*)d_in[12];
    const float* postW2 = (const float*)d_in[13];
    const float* postB2 = (const float*)d_in[14];
    const float* linW2  = (const float*)d_in[15];
    const float* linB2  = (const float*)d_in[16];
    const float* W2 = (const float*)d_in[17];
    const float* b2 = (const float*)d_in[18];
    float* out = (float*)d_out;

    const int* src = ei;
    const int* dst = ei + EE;

    // prep + CSR build
    k_prep<<<422, 256>>>(preW1, preW2, postW1, postB1, linW1, linB1,
                         postW2, postB2, linW2, linB2);
    k_deg<<<(EE + 255) / 256, 256>>>(dst);
    k_scan<<<1, 1024>>>();
    k_fill<<<(EE + 255) / 256, 256>>>(src, dst);

    // h0 = leaky_relu(x @ W0 + b0)
    k_gemm<128, 64, 1, -1, -1, -1, 0><<<(NN + 127) / 128, 256>>>(x, W0, b0, NN);

    // layer 1
    k_gemm<64, 128, 0, 0, 3, -2, 1><<<(NN + 63) / 64, 256>>>(0, 0, 0, NN);
    k_agg<<<(NN + 3) / 4, 256>>>(preB1);
    k_hmma<0, 0><<<(NN + 127) / 128, 256>>>(0, 0, 0);

    // layer 2 (HMMA GEMM fuses relu + out = h . W2 + b2)
    k_gemm<64, 128, 0, 0, 4, -2, 1><<<(NN + 63) / 64, 256>>>(0, 0, 0, NN);
    k_agg<<<(NN + 3) / 4, 256>>>(preB2);
    k_hmma<1, 1><<<(NN + 127) / 128, 256>>>(W2, b2, out);
}